// round 3
// baseline (speedup 1.0000x reference)
#include <cuda_runtime.h>
#include <cuda_bf16.h>
#include <math.h>

#define MAX_NODES 1000000

// Padded, pre-scaled nodal displacement: {ux*u_c, uy*u_c, th*theta_c, 0}
__device__ float4 g_pred4[MAX_NODES];
// Padded per-node internal force accumulator (w unused)
__device__ float4 g_Fint4[MAX_NODES];
__device__ double g_acc[2];     // [0] = sum(R_free^2), [1] = sum(F_free^2)
__device__ unsigned g_done;     // last-block ticket for node_kernel

// ---------------------------------------------------------------------------
// Kernel 1: prep — scale/pad pred_raw into g_pred4, zero g_Fint4 / g_acc / g_done
// ---------------------------------------------------------------------------
__global__ void prep_kernel(const float* __restrict__ pred_raw,
                            const float* __restrict__ u_c,
                            const float* __restrict__ theta_c,
                            int N)
{
    int i = blockIdx.x * blockDim.x + threadIdx.x;
    if (i < N) {
        float su = __ldg(u_c);
        float st = __ldg(theta_c);
        float x = pred_raw[3 * i + 0];
        float y = pred_raw[3 * i + 1];
        float t = pred_raw[3 * i + 2];
        g_pred4[i] = make_float4(x * su, y * su, t * st, 0.f);
        g_Fint4[i] = make_float4(0.f, 0.f, 0.f, 0.f);
    }
    if (i == 0) { g_acc[0] = 0.0; g_acc[1] = 0.0; g_done = 0u; }
}

// ---------------------------------------------------------------------------
// Kernel 2: element pass — 2 elements/thread, float4 gathers, v4 RED scatter
// ---------------------------------------------------------------------------
#define ETB 256          // threads per block
#define EPB (2 * ETB)    // elements per block

__device__ __forceinline__ void elem_compute(
    float c, float s, int2 cn, float L, float EA, float EI)
{
    float4 dA = __ldg(&g_pred4[cn.x]);   // {ux, uy, th_scaled, 0}
    float4 dB = __ldg(&g_pred4[cn.y]);

    float thA = -dA.z;
    float thB = -dB.z;

    float u_A =  c * dA.x + s * dA.y;
    float w_A = -s * dA.x + c * dA.y;
    float u_B =  c * dB.x + s * dB.y;
    float w_B = -s * dB.x + c * dB.y;

    float inv_l = 1.0f / L;
    float ea_l  = EA * inv_l;
    float ei_l  = EI * inv_l;
    float ei_l2 = ei_l * inv_l;
    float ei_l3 = ei_l2 * inv_l;

    float dw = w_A - w_B;
    float f0 = ea_l * (u_A - u_B);
    float f1 = 12.0f * ei_l3 * dw + 6.0f * ei_l2 * (thA + thB);
    float f2 = 6.0f * ei_l2 * dw + 4.0f * ei_l * thA + 2.0f * ei_l * thB;
    float f5 = 6.0f * ei_l2 * dw + 2.0f * ei_l * thA + 4.0f * ei_l * thB;

    float fAx = c * f0 - s * f1;
    float fAy = s * f0 + c * f1;

    float4* pA = &g_Fint4[cn.x];
    asm volatile("red.global.add.v4.f32 [%0], {%1, %2, %3, %4};"
                 :: "l"(pA), "f"(fAx), "f"(fAy), "f"(-f2), "f"(0.f)
                 : "memory");
    float4* pB = &g_Fint4[cn.y];
    asm volatile("red.global.add.v4.f32 [%0], {%1, %2, %3, %4};"
                 :: "l"(pB), "f"(-fAx), "f"(-fAy), "f"(-f5), "f"(0.f)
                 : "memory");
}

__global__ void __launch_bounds__(ETB)
elem_kernel(const float* __restrict__ elem_len,
            const float* __restrict__ prop_E,
            const float* __restrict__ prop_A,
            const float* __restrict__ prop_I,
            const float* __restrict__ dirs,     // [E,3]
            const int2*  __restrict__ conn,     // [E]
            int E)
{
    __shared__ float sdir[3 * EPB];
    int base = blockIdx.x * EPB;

    // coalesced staging of dirs for this block's EPB elements
    int lim3 = 3 * E;
    #pragma unroll
    for (int k = 0; k < 6; ++k) {
        int t = threadIdx.x + k * ETB;
        int g = base * 3 + t;
        sdir[t] = (g < lim3) ? dirs[g] : 0.f;
    }
    __syncthreads();

    int e0 = base + threadIdx.x;
    int e1 = e0 + ETB;
    bool v0 = (e0 < E);
    bool v1 = (e1 < E);

    // front-batch all per-element loads (max MLP)
    int2  cn0 = v0 ? conn[e0] : make_int2(0, 0);
    int2  cn1 = v1 ? conn[e1] : make_int2(0, 0);
    float L0  = v0 ? elem_len[e0] : 1.f;
    float L1  = v1 ? elem_len[e1] : 1.f;
    float pe0 = v0 ? prop_E[e0] : 0.f;
    float pe1 = v1 ? prop_E[e1] : 0.f;
    float pa0 = v0 ? prop_A[e0] : 0.f;
    float pa1 = v1 ? prop_A[e1] : 0.f;
    float pi0 = v0 ? prop_I[e0] : 0.f;
    float pi1 = v1 ? prop_I[e1] : 0.f;

    float c0 = sdir[3 * threadIdx.x + 0];
    float s0 = sdir[3 * threadIdx.x + 2];
    float c1 = sdir[3 * (threadIdx.x + ETB) + 0];
    float s1 = sdir[3 * (threadIdx.x + ETB) + 2];

    if (v0) elem_compute(c0, s0, cn0, L0, pe0 * pa0, pe0 * pi0);
    if (v1) elem_compute(c1, s1, cn1, L1, pe1 * pa1, pe1 * pi1);
}

// ---------------------------------------------------------------------------
// Kernel 3: node pass — masked residual reduction + fused final divide
// ---------------------------------------------------------------------------
__global__ void __launch_bounds__(256)
node_kernel(const float* __restrict__ F_ext,
            const float* __restrict__ bc_disp,
            const float* __restrict__ bc_rot,
            float* __restrict__ out,
            int N)
{
    int i = blockIdx.x * blockDim.x + threadIdx.x;

    float r2 = 0.f, f2 = 0.f;
    if (i < N) {
        float md = 1.0f - bc_disp[i];
        float mr = 1.0f - bc_rot[i];

        float4 Fi = g_Fint4[i];
        float Fe0 = F_ext[3 * i + 0];
        float Fe1 = F_ext[3 * i + 1];
        float Fe2 = F_ext[3 * i + 2];

        float R0 = (Fi.x - Fe0) * md;
        float R1 = (Fi.y - Fe1) * md;
        float R2 = (Fi.z - Fe2) * mr;
        float G0 = Fe0 * md;
        float G1 = Fe1 * md;
        float G2 = Fe2 * mr;

        r2 = R0 * R0 + R1 * R1 + R2 * R2;
        f2 = G0 * G0 + G1 * G1 + G2 * G2;
    }

    for (int off = 16; off > 0; off >>= 1) {
        r2 += __shfl_down_sync(0xffffffffu, r2, off);
        f2 += __shfl_down_sync(0xffffffffu, f2, off);
    }

    __shared__ float sr[8], sf[8];
    int lane = threadIdx.x & 31;
    int wid  = threadIdx.x >> 5;
    if (lane == 0) { sr[wid] = r2; sf[wid] = f2; }
    __syncthreads();

    if (wid == 0) {
        float rr = (lane < 8) ? sr[lane] : 0.f;
        float ff = (lane < 8) ? sf[lane] : 0.f;
        for (int off = 4; off > 0; off >>= 1) {
            rr += __shfl_down_sync(0xffffffffu, rr, off);
            ff += __shfl_down_sync(0xffffffffu, ff, off);
        }
        if (lane == 0) {
            atomicAdd(&g_acc[0], (double)rr);
            atomicAdd(&g_acc[1], (double)ff);
            // last-block-done: final divide without a separate kernel
            __threadfence();
            unsigned ticket = atomicAdd(&g_done, 1u);
            if (ticket == gridDim.x - 1) {
                double fn = g_acc[1];
                if (fn < 1e-30) fn = 1e-30;
                out[0] = (float)(g_acc[0] / fn);
            }
        }
    }
}

// ---------------------------------------------------------------------------
// Launch
// ---------------------------------------------------------------------------
extern "C" void kernel_launch(void* const* d_in, const int* in_sizes, int n_in,
                              void* d_out, int out_size)
{
    const float* pred_raw = (const float*)d_in[0];   // [N,3]
    const float* u_c      = (const float*)d_in[1];   // [1]
    const float* theta_c  = (const float*)d_in[2];   // [1]
    const float* elem_len = (const float*)d_in[3];   // [E]
    const float* prop_E   = (const float*)d_in[4];   // [E]
    const float* prop_A   = (const float*)d_in[5];   // [E]
    const float* prop_I   = (const float*)d_in[6];   // [E]
    const float* dirs     = (const float*)d_in[7];   // [E,3]
    const float* F_ext    = (const float*)d_in[8];   // [N,3]
    const float* bc_disp  = (const float*)d_in[9];   // [N,1]
    const float* bc_rot   = (const float*)d_in[10];  // [N,1]
    const int2*  conn     = (const int2*)d_in[11];   // [E,2]

    int N = in_sizes[0] / 3;
    int E = in_sizes[3];

    float* out = (float*)d_out;

    prep_kernel<<<(N + 255) / 256, 256>>>(pred_raw, u_c, theta_c, N);
    elem_kernel<<<(E + EPB - 1) / EPB, ETB>>>(elem_len, prop_E, prop_A, prop_I,
                                              dirs, conn, E);
    node_kernel<<<(N + 255) / 256, 256>>>(F_ext, bc_disp, bc_rot, out, N);
}